// round 6
// baseline (speedup 1.0000x reference)
#include <cuda_runtime.h>

// Sampler: out[row] = argmax_v( temp==0 ? logits[row,v]
//                                        : logits[row,v]/temp - log(max(noise[row,v],1e-10)) )
// B=128 rows, V=128000. Memory-bound streaming argmax.
// OUTPUT: float32 (index values stored as floats — harness compares as float).
//
// Shapes derived from in_sizes only:
//   B = smallest input's element count (temperatures)
//   V = largest input's element count / B
// logits vs exp_noise disambiguated on-device: exp_noise (Exponential) is
// strictly >= 0; logits ~N(0,1) has negatives among 8192 samples w.p. ~1.

#define NTHREADS 1024

__device__ int g_a_is_logits;   // 1 if candidate A (first big input) is logits

__global__ void classify_kernel(const float* __restrict__ a)
{
    bool neg = false;
    for (int i = threadIdx.x; i < 8192; i += blockDim.x)
        neg |= (a[i] < 0.0f);
    int any = __syncthreads_or((int)neg);
    if (threadIdx.x == 0) g_a_is_logits = (any != 0) ? 1 : 0;
}

__device__ __forceinline__ void take_better(float ov, int oi, float& bv, int& bi) {
    // first-occurrence tie-break (lower index wins), matching jnp.argmax
    if (ov > bv || (ov == bv && oi < bi)) { bv = ov; bi = oi; }
}

__global__ __launch_bounds__(NTHREADS, 1)
void sampler_argmax_kernel(const float* __restrict__ bigA,
                           const float* __restrict__ bigB,
                           const float* __restrict__ temps,
                           float* __restrict__ out,
                           int V)
{
    const float* __restrict__ logits = g_a_is_logits ? bigA : bigB;
    const float* __restrict__ noise  = g_a_is_logits ? bigB : bigA;

    const int row = blockIdx.x;
    const int tid = threadIdx.x;
    const size_t roff = (size_t)row * (size_t)V;
    const float t = temps[row];

    float bv = __int_as_float(0xff800000);  // -inf
    int   bi = 0x7fffffff;

    if ((V & 3) == 0) {
        const float4* __restrict__ l4 = reinterpret_cast<const float4*>(logits + roff);
        const float4* __restrict__ n4 = reinterpret_cast<const float4*>(noise + roff);
        const int NV4 = V >> 2;

        if (t == 0.0f) {
            // Greedy: plain argmax, exp_noise never read.
            for (int i = tid; i < NV4; i += NTHREADS) {
                float4 l = l4[i];
                int b = i << 2;
                if (l.x > bv) { bv = l.x; bi = b;     }
                if (l.y > bv) { bv = l.y; bi = b + 1; }
                if (l.z > bv) { bv = l.z; bi = b + 2; }
                if (l.w > bv) { bv = l.w; bi = b + 3; }
            }
        } else {
            const float invT = 1.0f / t;
            for (int i = tid; i < NV4; i += NTHREADS) {
                float4 l = l4[i];
                float4 e = n4[i];
                float s0 = l.x * invT - __logf(fmaxf(e.x, 1e-10f));
                float s1 = l.y * invT - __logf(fmaxf(e.y, 1e-10f));
                float s2 = l.z * invT - __logf(fmaxf(e.z, 1e-10f));
                float s3 = l.w * invT - __logf(fmaxf(e.w, 1e-10f));
                int b = i << 2;
                if (s0 > bv) { bv = s0; bi = b;     }
                if (s1 > bv) { bv = s1; bi = b + 1; }
                if (s2 > bv) { bv = s2; bi = b + 2; }
                if (s3 > bv) { bv = s3; bi = b + 3; }
            }
        }
    } else {
        // scalar fallback (V not divisible by 4)
        if (t == 0.0f) {
            for (int i = tid; i < V; i += NTHREADS) {
                float v = logits[roff + i];
                if (v > bv) { bv = v; bi = i; }
            }
        } else {
            const float invT = 1.0f / t;
            for (int i = tid; i < V; i += NTHREADS) {
                float v = logits[roff + i] * invT
                        - __logf(fmaxf(noise[roff + i], 1e-10f));
                if (v > bv) { bv = v; bi = i; }
            }
        }
    }

    // ---- intra-warp reduction ----
    const unsigned full = 0xffffffffu;
    #pragma unroll
    for (int o = 16; o > 0; o >>= 1) {
        float ov = __shfl_down_sync(full, bv, o);
        int   oi = __shfl_down_sync(full, bi, o);
        take_better(ov, oi, bv, bi);
    }

    // ---- cross-warp reduction ----
    __shared__ float s_val[32];
    __shared__ int   s_idx[32];
    const int wid = tid >> 5;
    const int lid = tid & 31;
    if (lid == 0) { s_val[wid] = bv; s_idx[wid] = bi; }
    __syncthreads();

    if (wid == 0) {
        bv = s_val[lid];
        bi = s_idx[lid];
        #pragma unroll
        for (int o = 16; o > 0; o >>= 1) {
            float ov = __shfl_down_sync(full, bv, o);
            int   oi = __shfl_down_sync(full, bi, o);
            take_better(ov, oi, bv, bi);
        }
        if (lid == 0) out[row] = (float)bi;   // FLOAT output: index as float32
    }
}

extern "C" void kernel_launch(void* const* d_in, const int* in_sizes, int n_in,
                              void* d_out, int out_size)
{
    (void)out_size;  // shapes come from in_sizes only

    // temps = smallest input; the two largest are the [B,V] arrays.
    int temp_i = 0;
    for (int i = 1; i < n_in; i++)
        if (in_sizes[i] < in_sizes[temp_i]) temp_i = i;

    int big0 = -1, big1 = -1;
    for (int i = 0; i < n_in; i++) {
        if (i == temp_i) continue;
        if (big0 < 0 || in_sizes[i] > in_sizes[big0]) { big1 = big0; big0 = i; }
        else if (big1 < 0 || in_sizes[i] > in_sizes[big1]) { big1 = i; }
    }

    const int B = in_sizes[temp_i];          // 128
    const int V = in_sizes[big0] / B;        // 128000

    const float* bigA  = (const float*)d_in[big0];
    const float* bigB  = (const float*)d_in[big1];
    const float* temps = (const float*)d_in[temp_i];
    float* out = (float*)d_out;

    classify_kernel<<<1, 256>>>(bigA);
    sampler_argmax_kernel<<<B, NTHREADS>>>(bigA, bigB, temps, out, V);
}